// round 11
// baseline (speedup 1.0000x reference)
#include <cuda_runtime.h>
#include <math.h>

// Problem constants (fixed by the reference)
#define MM 3
#define BB 65536
#define NN 360
#define MS_ITERS 10
#define KAPPA 10.0f
#define LOG2E 1.4426950408889634f
#define KL2E (KAPPA * LOG2E)

#define WARPS_PER_BLOCK 4
#define THREADS_PER_BLOCK (WARPS_PER_BLOCK * 32)
#define NPAIR 6   // 12 bins per lane = 6 packed pairs

typedef unsigned long long u64;

__device__ __forceinline__ float ex2f(float x) {
    float y;
    asm("ex2.approx.ftz.f32 %0, %1;" : "=f"(y) : "f"(x));
    return y;
}

__device__ __forceinline__ u64 pack2(float lo, float hi) {
    u64 r;
    asm("mov.b64 %0, {%1, %2};" : "=l"(r) : "f"(lo), "f"(hi));
    return r;
}
__device__ __forceinline__ void unpack2(u64 v, float& lo, float& hi) {
    asm("mov.b64 {%0, %1}, %2;" : "=f"(lo), "=f"(hi) : "l"(v));
}
__device__ __forceinline__ u64 fma2(u64 a, u64 b, u64 c) {
    u64 d;
    asm("fma.rn.f32x2 %0, %1, %2, %3;" : "=l"(d) : "l"(a), "l"(b), "l"(c));
    return d;
}
__device__ __forceinline__ u64 mul2(u64 a, u64 b) {
    u64 d;
    asm("mul.rn.f32x2 %0, %1, %2;" : "=l"(d) : "l"(a), "l"(b));
    return d;
}
__device__ __forceinline__ u64 add2(u64 a, u64 b) {
    u64 d;
    asm("add.rn.f32x2 %0, %1, %2;" : "=l"(d) : "l"(a), "l"(b));
    return d;
}

// scalar warp sum (5 SHFL.32)
__device__ __forceinline__ float warp_sum(float v) {
    v += __shfl_xor_sync(0xFFFFFFFFu, v, 16);
    v += __shfl_xor_sync(0xFFFFFFFFu, v, 8);
    v += __shfl_xor_sync(0xFFFFFFFFu, v, 4);
    v += __shfl_xor_sync(0xFFFFFFFFu, v, 2);
    v += __shfl_xor_sync(0xFFFFFFFFu, v, 1);
    return v;
}

// Parity-interleaved pair reduction: sums BOTH a and b across the warp with
// only 6 SHFL.32. Even lanes carry the a-chain, odd lanes the b-chain.
__device__ __forceinline__ void preduce2(float& a, float& b, int lane) {
    const bool odd = lane & 1;
    float z = odd ? b : a;
    float o = odd ? a : b;
    z += __shfl_xor_sync(0xFFFFFFFFu, o, 1);
    z += __shfl_xor_sync(0xFFFFFFFFu, z, 2);
    z += __shfl_xor_sync(0xFFFFFFFFu, z, 4);
    z += __shfl_xor_sync(0xFFFFFFFFu, z, 8);
    z += __shfl_xor_sync(0xFFFFFFFFu, z, 16);
    float other = __shfl_xor_sync(0xFFFFFFFFu, z, 1);
    a = odd ? other : z;
    b = odd ? z : other;
}

// logits float4 -> packed exps (e0,e1),(e2,e3) via ex2(x*log2e)
__device__ __forceinline__ void conv4(const float4& xx, u64& elo, u64& ehi) {
    u64 lo = mul2(pack2(xx.x, xx.y), pack2(LOG2E, LOG2E));
    u64 hi = mul2(pack2(xx.z, xx.w), pack2(LOG2E, LOG2E));
    float a0, a1, a2, a3;
    unpack2(lo, a0, a1);
    unpack2(hi, a2, a3);
    elo = pack2(ex2f(a0), ex2f(a1));
    ehi = pack2(ex2f(a2), ex2f(a3));
}

// horizontal sum of 6 packed pairs -> scalar
__device__ __forceinline__ float hsum6(const u64* e) {
    u64 acc = add2(add2(e[0], e[1]), add2(add2(e[2], e[3]), add2(e[4], e[5])));
    float lo, hi;
    unpack2(acc, lo, hi);
    return lo + hi;
}

__global__ void __launch_bounds__(THREADS_PER_BLOCK, 12)
angle_ensemble_kernel(const float* __restrict__ von,      // [M, B, N]
                      const float* __restrict__ sin_vec,  // [B, 2]
                      const float* __restrict__ W1,       // [4, 128]
                      const float* __restrict__ b1,       // [128]
                      const float* __restrict__ W2,       // [128, 2]
                      const float* __restrict__ b2,       // [2]
                      float* __restrict__ out)            // [B, 2]
{
    // Lane-major (cos,cos,sin,sin) table, pre-scaled by KAPPA*log2(e).
    // Entry [p*32+lane] = (c(n0), c(n0+1), s(n0), s(n0+1)) for the pair of
    // bins this lane owns in pair-slot p. Shared by ALL warps/b's -> keeping
    // it in smem (3 KB) instead of registers frees ~24 regs per thread.
    __shared__ float4 s_tab[NPAIR * 32];
    __shared__ float s_W1[4 * 128];
    __shared__ float s_b1[128];
    __shared__ float s_W2[128 * 2];
    __shared__ float s_b2[2];

    const int tid = threadIdx.x;
    for (int idx = tid; idx < NPAIR * 32; idx += THREADS_PER_BLOCK) {
        int p = idx >> 5, ln = idx & 31;
        int n0 = 4 * ln + 128 * (p >> 1) + 2 * (p & 1);  // even, pair = n0,n0+1
        float c0 = 0.0f, s0 = 0.0f, c1 = 0.0f, s1 = 0.0f;
        if (n0 < NN) {
            float th0 = 6.283185307179586f * (float)n0 / (float)NN;
            float th1 = 6.283185307179586f * (float)(n0 + 1) / (float)NN;
            sincosf(th0, &s0, &c0);
            sincosf(th1, &s1, &c1);
        }
        s_tab[idx] = make_float4(KL2E * c0, KL2E * c1, KL2E * s0, KL2E * s1);
    }
    for (int i = tid; i < 4 * 128; i += THREADS_PER_BLOCK) s_W1[i] = W1[i];
    for (int i = tid; i < 128; i += THREADS_PER_BLOCK)     s_b1[i] = b1[i];
    for (int i = tid; i < 256; i += THREADS_PER_BLOCK)     s_W2[i] = W2[i];
    if (tid < 2) s_b2[tid] = b2[tid];
    __syncthreads();

    const int warp = tid >> 5;
    const int lane = tid & 31;
    const int b = blockIdx.x * WARPS_PER_BLOCK + warp;
    const float* __restrict__ base = von + (size_t)b * NN;

    const float NEG_INF = __int_as_float(0xff800000);
    const float4 NEG_INF4 = make_float4(NEG_INF, NEG_INF, NEG_INF, NEG_INF);
    const bool v2 = (lane + 64) < 90;  // float4 chunk k=2 validity

    // ---- Mixture of softmaxes, sequential rows with scale-free folding ----
    // acc ∝ u_a/S_a + u_b/S_b + u_c/S_c up to a uniform positive scale
    // (uniform scale is irrelevant: every consumer normalizes the resultant).
    // Masked tail logits = -inf -> ex2 -> 0 -> acc = 0; no masking later.
    u64 acc[NPAIR];   // row exps, progressively folded
    float S0, S1;
    {
        const float4* r0 = (const float4*)base;
        float4 q0 = r0[lane], q1 = r0[lane + 32], q2 = v2 ? r0[lane + 64] : NEG_INF4;
        conv4(q0, acc[0], acc[1]); conv4(q1, acc[2], acc[3]); conv4(q2, acc[4], acc[5]);
        S0 = warp_sum(hsum6(acc));
    }
    {
        const float4* r1 = (const float4*)(base + (size_t)BB * NN);
        float4 q0 = r1[lane], q1 = r1[lane + 32], q2 = v2 ? r1[lane + 64] : NEG_INF4;
        u64 e[NPAIR];
        conv4(q0, e[0], e[1]); conv4(q1, e[2], e[3]); conv4(q2, e[4], e[5]);
        S1 = warp_sum(hsum6(e));
        u64 s12 = pack2(S1, S1), s02 = pack2(S0, S0);
#pragma unroll
        for (int p = 0; p < NPAIR; p++)
            acc[p] = fma2(acc[p], s12, mul2(e[p], s02));  // u_a*S_b + u_b*S_a
    }
    {
        const float4* r2 = (const float4*)(base + (size_t)2 * BB * NN);
        float4 q0 = r2[lane], q1 = r2[lane + 32], q2 = v2 ? r2[lane + 64] : NEG_INF4;
        u64 e[NPAIR];
        conv4(q0, e[0], e[1]); conv4(q1, e[2], e[3]); conv4(q2, e[4], e[5]);
        float S2 = warp_sum(hsum6(e));
        float S01 = S0 * S1;
        u64 s22 = pack2(S2, S2), s012 = pack2(S01, S01);
#pragma unroll
        for (int p = 0; p < NPAIR; p++)
            acc[p] = fma2(acc[p], s22, mul2(e[p], s012));
    }

    // ---- init: weighted circular mean (table from smem) ----
    float ct, st;
    {
        u64 C2 = 0ull, S2v = 0ull;
#pragma unroll
        for (int p = 0; p < NPAIR; p++) {
            float4 t = s_tab[p * 32 + lane];
            C2 = fma2(acc[p], pack2(t.x, t.y), C2);
            S2v = fma2(acc[p], pack2(t.z, t.w), S2v);
        }
        float c0, c1, s0, s1;
        unpack2(C2, c0, c1);
        unpack2(S2v, s0, s1);
        float C = c0 + c1, S = s0 + s1;
        preduce2(C, S, lane);
        float r = rsqrtf(fmaf(S, S, C * C));
        ct = C * r;
        st = S * r;
    }

    // ---- mean-shift iterations ----
    // w_n * exp(K*cos(theta-theta_n)) = w_n * ex2( ct*cns_n + st*sns_n )
    for (int it = 0; it < MS_ITERS; it++) {
        u64 ct2 = pack2(ct, ct);
        u64 st2 = pack2(st, st);
        u64 Ca = 0ull, Sa = 0ull;
#pragma unroll
        for (int p = 0; p < NPAIR; p++) {
            float4 t = s_tab[p * 32 + lane];
            u64 cns = pack2(t.x, t.y);
            u64 sns = pack2(t.z, t.w);
            u64 a2 = fma2(ct2, cns, mul2(st2, sns));
            float a0, a1;
            unpack2(a2, a0, a1);
            u64 k2 = mul2(acc[p], pack2(ex2f(a0), ex2f(a1)));
            Ca = fma2(k2, cns, Ca);
            Sa = fma2(k2, sns, Sa);
        }
        float c0, c1, s0, s1;
        unpack2(Ca, c0, c1);
        unpack2(Sa, s0, s1);
        float Ci = c0 + c1, Si = s0 + s1;
        preduce2(Ci, Si, lane);
        float rr = rsqrtf(fmaf(Si, Si, Ci * Ci));
        float nct = Ci * rr;
        float nst = Si * rr;
        float d = fabsf(nct - ct) + fabsf(nst - st);
        ct = nct;
        st = nst;
        // Warp-uniform early exit: remaining reference iterations move the
        // output by ~0.65*d -> ~3e-4 worst case, under the 1e-3 tolerance.
        if (d < 5e-4f) break;
    }

    // ---- tiny MLP head: fused = [sin_vec, cos t, sin t] -> 128 relu -> 2 ----
    float2 sv = *(const float2*)(sin_vec + 2 * (size_t)b);

    float o0 = 0.0f, o1 = 0.0f;
#pragma unroll
    for (int q = 0; q < 4; q++) {
        int j = lane * 4 + q;  // 0..127
        float h = s_b1[j];
        h = fmaf(sv.x, s_W1[0 * 128 + j], h);
        h = fmaf(sv.y, s_W1[1 * 128 + j], h);
        h = fmaf(ct,   s_W1[2 * 128 + j], h);
        h = fmaf(st,   s_W1[3 * 128 + j], h);
        h = fmaxf(h, 0.0f);
        o0 = fmaf(h, s_W2[j * 2 + 0], o0);
        o1 = fmaf(h, s_W2[j * 2 + 1], o1);
    }
    preduce2(o0, o1, lane);

    if (lane == 0) {
        o0 += s_b2[0];
        o1 += s_b2[1];
        float nrm = sqrtf(fmaf(o0, o0, o1 * o1));
        nrm = fmaxf(nrm, 1e-12f);
        float inv = 1.0f / nrm;
        *(float2*)(out + 2 * (size_t)b) = make_float2(o0 * inv, o1 * inv);
    }
}

extern "C" void kernel_launch(void* const* d_in, const int* in_sizes, int n_in,
                              void* d_out, int out_size) {
    const float* von     = (const float*)d_in[0];  // [3, 65536, 360]
    const float* sin_vec = (const float*)d_in[1];  // [65536, 2]
    const float* W1      = (const float*)d_in[2];  // [4, 128]
    const float* b1      = (const float*)d_in[3];  // [128]
    const float* W2      = (const float*)d_in[4];  // [128, 2]
    const float* b2      = (const float*)d_in[5];  // [2]
    float* out = (float*)d_out;                    // [65536, 2]

    const int blocks = BB / WARPS_PER_BLOCK;  // 16384
    angle_ensemble_kernel<<<blocks, THREADS_PER_BLOCK>>>(
        von, sin_vec, W1, b1, W2, b2, out);
}

// round 12
// speedup vs baseline: 1.3236x; 1.3236x over previous
#include <cuda_runtime.h>
#include <math.h>

// Problem constants (fixed by the reference)
#define MM 3
#define BB 65536
#define NN 360
#define MS_ITERS 10
#define KAPPA 10.0f
#define LOG2E 1.4426950408889634f
#define KL2E (KAPPA * LOG2E)

#define WARPS_PER_BLOCK 4
#define THREADS_PER_BLOCK (WARPS_PER_BLOCK * 32)
#define NPAIR 6   // 12 bins per lane = 6 packed pairs

typedef unsigned long long u64;

// Precomputed constant tables (built once per launch by init_tables).
// g_tab[p*32 + lane] = (KL2E*cos(n0), KL2E*cos(n0+1), KL2E*sin(n0), KL2E*sin(n0+1))
// for the bin pair this lane owns in pair-slot p.
__device__ float4 g_tab[NPAIR * 32];
// g_mlp[slot*32 + lane]: per-lane packed MLP params (slot-major for coalescing)
//  slot 0..3: W1 rows 0..3 at cols [4l..4l+3]
//  slot 4:    b1[4l..4l+3]
//  slot 5:    (W2[4l][0],W2[4l][1],W2[4l+1][0],W2[4l+1][1])
//  slot 6:    (W2[4l+2][0],W2[4l+2][1],W2[4l+3][0],W2[4l+3][1])
//  slot 7:    (b2[0], b2[1], 0, 0)
__device__ float4 g_mlp[8 * 32];

__global__ void init_tables(const float* __restrict__ W1,
                            const float* __restrict__ b1,
                            const float* __restrict__ W2,
                            const float* __restrict__ b2) {
    int t = threadIdx.x;
    if (t < NPAIR * 32) {
        int p = t >> 5, ln = t & 31;
        int n0 = 4 * ln + 128 * (p >> 1) + 2 * (p & 1);
        float c0 = 0.0f, s0 = 0.0f, c1 = 0.0f, s1 = 0.0f;
        if (n0 < NN) {
            float th0 = 6.283185307179586f * (float)n0 / (float)NN;
            float th1 = 6.283185307179586f * (float)(n0 + 1) / (float)NN;
            sincosf(th0, &s0, &c0);
            sincosf(th1, &s1, &c1);
        }
        g_tab[t] = make_float4(KL2E * c0, KL2E * c1, KL2E * s0, KL2E * s1);
    } else if (t < NPAIR * 32 + 32) {
        int l = t - NPAIR * 32;
        int j = 4 * l;
#pragma unroll
        for (int r = 0; r < 4; r++)
            g_mlp[r * 32 + l] = make_float4(W1[r * 128 + j], W1[r * 128 + j + 1],
                                            W1[r * 128 + j + 2], W1[r * 128 + j + 3]);
        g_mlp[4 * 32 + l] = make_float4(b1[j], b1[j + 1], b1[j + 2], b1[j + 3]);
        g_mlp[5 * 32 + l] = make_float4(W2[2 * j + 0], W2[2 * j + 1],
                                        W2[2 * j + 2], W2[2 * j + 3]);
        g_mlp[6 * 32 + l] = make_float4(W2[2 * j + 4], W2[2 * j + 5],
                                        W2[2 * j + 6], W2[2 * j + 7]);
        g_mlp[7 * 32 + l] = make_float4(b2[0], b2[1], 0.0f, 0.0f);
    }
}

__device__ __forceinline__ float ex2f(float x) {
    float y;
    asm("ex2.approx.ftz.f32 %0, %1;" : "=f"(y) : "f"(x));
    return y;
}

__device__ __forceinline__ u64 pack2(float lo, float hi) {
    u64 r;
    asm("mov.b64 %0, {%1, %2};" : "=l"(r) : "f"(lo), "f"(hi));
    return r;
}
__device__ __forceinline__ void unpack2(u64 v, float& lo, float& hi) {
    asm("mov.b64 {%0, %1}, %2;" : "=f"(lo), "=f"(hi) : "l"(v));
}
__device__ __forceinline__ u64 fma2(u64 a, u64 b, u64 c) {
    u64 d;
    asm("fma.rn.f32x2 %0, %1, %2, %3;" : "=l"(d) : "l"(a), "l"(b), "l"(c));
    return d;
}
__device__ __forceinline__ u64 mul2(u64 a, u64 b) {
    u64 d;
    asm("mul.rn.f32x2 %0, %1, %2;" : "=l"(d) : "l"(a), "l"(b));
    return d;
}
__device__ __forceinline__ u64 add2(u64 a, u64 b) {
    u64 d;
    asm("add.rn.f32x2 %0, %1, %2;" : "=l"(d) : "l"(a), "l"(b));
    return d;
}

// scalar warp sum (5 SHFL.32)
__device__ __forceinline__ float warp_sum(float v) {
    v += __shfl_xor_sync(0xFFFFFFFFu, v, 16);
    v += __shfl_xor_sync(0xFFFFFFFFu, v, 8);
    v += __shfl_xor_sync(0xFFFFFFFFu, v, 4);
    v += __shfl_xor_sync(0xFFFFFFFFu, v, 2);
    v += __shfl_xor_sync(0xFFFFFFFFu, v, 1);
    return v;
}

// Parity-interleaved pair reduction: sums BOTH a and b across the warp with
// only 6 SHFL.32. Even lanes carry the a-chain, odd lanes the b-chain.
__device__ __forceinline__ void preduce2(float& a, float& b, int lane) {
    const bool odd = lane & 1;
    float z = odd ? b : a;
    float o = odd ? a : b;
    z += __shfl_xor_sync(0xFFFFFFFFu, o, 1);
    z += __shfl_xor_sync(0xFFFFFFFFu, z, 2);
    z += __shfl_xor_sync(0xFFFFFFFFu, z, 4);
    z += __shfl_xor_sync(0xFFFFFFFFu, z, 8);
    z += __shfl_xor_sync(0xFFFFFFFFu, z, 16);
    float other = __shfl_xor_sync(0xFFFFFFFFu, z, 1);
    a = odd ? other : z;
    b = odd ? z : other;
}

// logits float4 -> packed exps (e0,e1),(e2,e3) via ex2(x*log2e)
__device__ __forceinline__ void conv4(const float4& xx, u64& elo, u64& ehi) {
    u64 lo = mul2(pack2(xx.x, xx.y), pack2(LOG2E, LOG2E));
    u64 hi = mul2(pack2(xx.z, xx.w), pack2(LOG2E, LOG2E));
    float a0, a1, a2, a3;
    unpack2(lo, a0, a1);
    unpack2(hi, a2, a3);
    elo = pack2(ex2f(a0), ex2f(a1));
    ehi = pack2(ex2f(a2), ex2f(a3));
}

// horizontal sum of 6 packed pairs -> scalar
__device__ __forceinline__ float hsum6(const u64* e) {
    u64 acc = add2(add2(e[0], e[1]), add2(add2(e[2], e[3]), add2(e[4], e[5])));
    float lo, hi;
    unpack2(acc, lo, hi);
    return lo + hi;
}

__global__ void __launch_bounds__(THREADS_PER_BLOCK, 9)
angle_ensemble_kernel(const float* __restrict__ von,      // [M, B, N]
                      const float* __restrict__ sin_vec,  // [B, 2]
                      float* __restrict__ out)            // [B, 2]
{
    const int tid = threadIdx.x;
    const int warp = tid >> 5;
    const int lane = tid & 31;
    const int b = blockIdx.x * WARPS_PER_BLOCK + warp;
    const float* __restrict__ base = von + (size_t)b * NN;

    const float NEG_INF = __int_as_float(0xff800000);
    const float4 NEG_INF4 = make_float4(NEG_INF, NEG_INF, NEG_INF, NEG_INF);
    const bool v2 = (lane + 64) < 90;  // float4 chunk k=2 validity

    // ---- Mixture of softmaxes ----
    // All 9 LDG.128 issued up front (front-batched); masked tail logits
    // -inf -> ex2 -> 0 -> w = 0, so no masking downstream.
    u64 w2[NPAIR];
    {
        const float4* r0 = (const float4*)base;
        const float4* r1 = (const float4*)(base + (size_t)BB * NN);
        const float4* r2 = (const float4*)(base + (size_t)2 * BB * NN);
        float4 xa0 = r0[lane], xa1 = r0[lane + 32], xa2 = v2 ? r0[lane + 64] : NEG_INF4;
        float4 xb0 = r1[lane], xb1 = r1[lane + 32], xb2 = v2 ? r1[lane + 64] : NEG_INF4;
        float4 xc0 = r2[lane], xc1 = r2[lane + 32], xc2 = v2 ? r2[lane + 64] : NEG_INF4;

        u64 ea[NPAIR], eb[NPAIR];
        conv4(xa0, ea[0], ea[1]); conv4(xa1, ea[2], ea[3]); conv4(xa2, ea[4], ea[5]);
        conv4(xb0, eb[0], eb[1]); conv4(xb1, eb[2], eb[3]); conv4(xb2, eb[4], eb[5]);

        float suma = hsum6(ea);
        float sumb = hsum6(eb);
        preduce2(suma, sumb, lane);
        u64 inva2, invb2;
        {
            float ia = __frcp_rn(suma), ib = __frcp_rn(sumb);
            inva2 = pack2(ia, ia);
            invb2 = pack2(ib, ib);
        }
#pragma unroll
        for (int p = 0; p < NPAIR; p++)
            w2[p] = fma2(eb[p], invb2, mul2(ea[p], inva2));

        // third row (reuse ea registers)
        conv4(xc0, ea[0], ea[1]); conv4(xc1, ea[2], ea[3]); conv4(xc2, ea[4], ea[5]);
        float sumc = warp_sum(hsum6(ea));
        float ic = __frcp_rn(sumc);
        u64 invc2 = pack2(ic, ic);
#pragma unroll
        for (int p = 0; p < NPAIR; p++) w2[p] = fma2(ea[p], invc2, w2[p]);
    }

    // ---- Load precomputed scaled bin table into registers; init mean ----
    u64 cns2[NPAIR], sns2[NPAIR];
    u64 C2 = 0ull, S2 = 0ull;
#pragma unroll
    for (int p = 0; p < NPAIR; p++) {
        float4 t = g_tab[p * 32 + lane];   // L2/L1-hot, coalesced
        cns2[p] = pack2(t.x, t.y);
        sns2[p] = pack2(t.z, t.w);
        C2 = fma2(w2[p], cns2[p], C2);
        S2 = fma2(w2[p], sns2[p], S2);
    }

    float ct, st;
    {
        float c0, c1, s0, s1;
        unpack2(C2, c0, c1);
        unpack2(S2, s0, s1);
        float C = c0 + c1, S = s0 + s1;
        preduce2(C, S, lane);
        float r = rsqrtf(fmaf(S, S, C * C));
        ct = C * r;   // cos(theta)
        st = S * r;   // sin(theta)
    }

    // ---- mean-shift iterations (linear-space weights) ----
    // w_n * exp(K*cos(theta-theta_n)) = w_n * ex2( ct*cns_n + st*sns_n )
    for (int it = 0; it < MS_ITERS; it++) {
        u64 ct2 = pack2(ct, ct);
        u64 st2 = pack2(st, st);
        u64 Ca = 0ull, Sa = 0ull;
#pragma unroll
        for (int p = 0; p < NPAIR; p++) {
            u64 a2 = fma2(ct2, cns2[p], mul2(st2, sns2[p]));
            float a0, a1;
            unpack2(a2, a0, a1);
            u64 k2 = mul2(w2[p], pack2(ex2f(a0), ex2f(a1)));
            Ca = fma2(k2, cns2[p], Ca);
            Sa = fma2(k2, sns2[p], Sa);
        }
        float c0, c1, s0, s1;
        unpack2(Ca, c0, c1);
        unpack2(Sa, s0, s1);
        float Ci = c0 + c1, Si = s0 + s1;
        preduce2(Ci, Si, lane);
        float rr = rsqrtf(fmaf(Si, Si, Ci * Ci));
        float nct = Ci * rr;
        float nst = Si * rr;
        float d = fabsf(nct - ct) + fabsf(nst - st);
        ct = nct;
        st = nst;
        // Warp-uniform early exit: remaining reference iterations move the
        // output well under the 1e-3 tolerance (measured rel_err ~4.4e-4).
        if (d < 5e-4f) break;
    }

    // ---- tiny MLP head from precomputed per-lane packed params ----
    float2 sv = *(const float2*)(sin_vec + 2 * (size_t)b);

    float4 w1r0 = g_mlp[0 * 32 + lane];
    float4 w1r1 = g_mlp[1 * 32 + lane];
    float4 w1r2 = g_mlp[2 * 32 + lane];
    float4 w1r3 = g_mlp[3 * 32 + lane];
    float4 bb1  = g_mlp[4 * 32 + lane];
    float4 w2a  = g_mlp[5 * 32 + lane];
    float4 w2b  = g_mlp[6 * 32 + lane];
    float4 bb2  = g_mlp[7 * 32 + lane];

    float h0 = fmaf(sv.x, w1r0.x, bb1.x); h0 = fmaf(sv.y, w1r1.x, h0);
    h0 = fmaf(ct, w1r2.x, h0); h0 = fmaf(st, w1r3.x, h0); h0 = fmaxf(h0, 0.0f);
    float h1 = fmaf(sv.x, w1r0.y, bb1.y); h1 = fmaf(sv.y, w1r1.y, h1);
    h1 = fmaf(ct, w1r2.y, h1); h1 = fmaf(st, w1r3.y, h1); h1 = fmaxf(h1, 0.0f);
    float h2 = fmaf(sv.x, w1r0.z, bb1.z); h2 = fmaf(sv.y, w1r1.z, h2);
    h2 = fmaf(ct, w1r2.z, h2); h2 = fmaf(st, w1r3.z, h2); h2 = fmaxf(h2, 0.0f);
    float h3 = fmaf(sv.x, w1r0.w, bb1.w); h3 = fmaf(sv.y, w1r1.w, h3);
    h3 = fmaf(ct, w1r2.w, h3); h3 = fmaxf(fmaf(st, w1r3.w, h3), 0.0f);

    u64 oacc = fma2(pack2(h0, h0), pack2(w2a.x, w2a.y), 0ull);
    oacc = fma2(pack2(h1, h1), pack2(w2a.z, w2a.w), oacc);
    oacc = fma2(pack2(h2, h2), pack2(w2b.x, w2b.y), oacc);
    oacc = fma2(pack2(h3, h3), pack2(w2b.z, w2b.w), oacc);
    float o0, o1;
    unpack2(oacc, o0, o1);
    preduce2(o0, o1, lane);

    if (lane == 0) {
        o0 += bb2.x;
        o1 += bb2.y;
        float nrm = sqrtf(fmaf(o0, o0, o1 * o1));
        nrm = fmaxf(nrm, 1e-12f);
        float inv = 1.0f / nrm;
        *(float2*)(out + 2 * (size_t)b) = make_float2(o0 * inv, o1 * inv);
    }
}

extern "C" void kernel_launch(void* const* d_in, const int* in_sizes, int n_in,
                              void* d_out, int out_size) {
    const float* von     = (const float*)d_in[0];  // [3, 65536, 360]
    const float* sin_vec = (const float*)d_in[1];  // [65536, 2]
    const float* W1      = (const float*)d_in[2];  // [4, 128]
    const float* b1      = (const float*)d_in[3];  // [128]
    const float* W2      = (const float*)d_in[4];  // [128, 2]
    const float* b2      = (const float*)d_in[5];  // [2]
    float* out = (float*)d_out;                    // [65536, 2]

    init_tables<<<1, NPAIR * 32 + 32>>>(W1, b1, W2, b2);
    const int blocks = BB / WARPS_PER_BLOCK;  // 16384
    angle_ensemble_kernel<<<blocks, THREADS_PER_BLOCK>>>(von, sin_vec, out);
}